// round 4
// baseline (speedup 1.0000x reference)
#include <cuda_runtime.h>
#include <cstdint>

#define B_  64
#define S_  512
#define H_  1024
#define L_  64
#define M_  (B_ * S_)      // 32768 rows

// ---------------- scratch (no allocations allowed) ----------------
__device__ float g_llh[B_];

// ================= Emissions GEMM =================
// emissions[m][l] = sum_k hs[m][k] * W[k][l] + bias[l]
// BM=128 rows, BN=64 cols (full L), BK=16. 256 threads.
// Thread (tx = tid%16, ty = tid/16): rows ty*8..+7, cols tx*4..+3.
#define BM 128
#define BN 64
#define BK 16
#define AS_ROW (BM / 4 + 1)   // float4 units per k-row (+1 pad)

__global__ __launch_bounds__(256) void gemm_kernel(
    const float* __restrict__ hs,
    const float* __restrict__ W,
    const float* __restrict__ bias,
    float* __restrict__ out)
{
    __shared__ float4 As4[BK][AS_ROW];     // transposed: As4[k][row/4]
    __shared__ float4 Bs4[BK][BN / 4];     // Bs4[k][col/4]

    const int tid = threadIdx.x;
    const int m0  = blockIdx.x * BM;
    const int tx  = tid & 15;    // col group -> cols tx*4..+3
    const int ty  = tid >> 4;    // row group -> rows ty*8..+7

    // ---- global load mapping (float4, 16B-aligned) ----
    // A tile: 128 rows x 16 k = 512 float4; thread loads f4 #tid (rows 0..63) and #tid+256
    const int a_row = tid >> 2;          // 0..63
    const int a_k   = (tid & 3) * 4;     // 0,4,8,12  (16B aligned within row)
    const float* hsA0 = hs + (size_t)(m0 + a_row)      * H_ + a_k;
    const float* hsA1 = hs + (size_t)(m0 + a_row + 64) * H_ + a_k;
    // B tile: 16 k x 64 cols = 256 float4
    const int b_k  = tid >> 4;           // 0..15
    const int b_c4 = tid & 15;           // 0..15
    const float* Wp = W + (size_t)b_k * L_ + b_c4 * 4;

    float acc[8][4];
    #pragma unroll
    for (int p = 0; p < 8; ++p)
        #pragma unroll
        for (int q = 0; q < 4; ++q) acc[p][q] = 0.0f;

    float4 a0 = *(const float4*)hsA0;
    float4 a1 = *(const float4*)hsA1;
    float4 bw = *(const float4*)Wp;

    float* As_f = (float*)As4;   // scalar alias for transposed staging (4B stores, always legal)

    const int NCH = H_ / BK;     // 64 chunks
    for (int kc = 0; kc < NCH; ++kc) {
        // stage current chunk (transposed scalar stores for A)
        As_f[(a_k + 0) * (AS_ROW * 4) + a_row] = a0.x;
        As_f[(a_k + 1) * (AS_ROW * 4) + a_row] = a0.y;
        As_f[(a_k + 2) * (AS_ROW * 4) + a_row] = a0.z;
        As_f[(a_k + 3) * (AS_ROW * 4) + a_row] = a0.w;
        As_f[(a_k + 0) * (AS_ROW * 4) + a_row + 64] = a1.x;
        As_f[(a_k + 1) * (AS_ROW * 4) + a_row + 64] = a1.y;
        As_f[(a_k + 2) * (AS_ROW * 4) + a_row + 64] = a1.z;
        As_f[(a_k + 3) * (AS_ROW * 4) + a_row + 64] = a1.w;
        Bs4[b_k][b_c4] = bw;
        __syncthreads();

        // prefetch next chunk
        if (kc + 1 < NCH) {
            a0 = *(const float4*)(hsA0 + (kc + 1) * BK);
            a1 = *(const float4*)(hsA1 + (kc + 1) * BK);
            bw = *(const float4*)(Wp + (size_t)(kc + 1) * BK * L_);
        }

        #pragma unroll
        for (int kk = 0; kk < BK; ++kk) {
            const float4 av0 = As4[kk][ty * 2];       // rows ty*8..+3
            const float4 av1 = As4[kk][ty * 2 + 1];   // rows ty*8+4..+7
            const float4 bv  = Bs4[kk][tx];           // cols tx*4..+3
            const float ar[8] = {av0.x, av0.y, av0.z, av0.w, av1.x, av1.y, av1.z, av1.w};
            const float br[4] = {bv.x, bv.y, bv.z, bv.w};
            #pragma unroll
            for (int p = 0; p < 8; ++p)
                #pragma unroll
                for (int q = 0; q < 4; ++q)
                    acc[p][q] = fmaf(ar[p], br[q], acc[p][q]);
        }
        __syncthreads();
    }

    // epilogue: add bias, scalar stores (emis base is only 4B-aligned: out+1)
    float bb[4];
    #pragma unroll
    for (int q = 0; q < 4; ++q) bb[q] = bias[tx * 4 + q];

    #pragma unroll
    for (int p = 0; p < 8; ++p) {
        const size_t r = (size_t)(m0 + ty * 8 + p) * L_ + tx * 4;
        #pragma unroll
        for (int q = 0; q < 4; ++q)
            out[r + q] = acc[p][q] + bb[q];
    }
}

// ================= CRF kernel =================
// One CTA per batch, 64 threads (thread j owns label j).
// Exp-domain scan: q_t[j] = (sum_i q_{t-1}[i] * E[i][j]) * exp(em[t][j]) * pending,
// E[i] = exp(trans[i][j]) per-thread registers. Renorm by block max every 8 steps,
// accumulated log-scale in c. Numerator fused at the end.
// labels are int32 on device (harness converts int64 -> int32).
__global__ __launch_bounds__(64) void crf_kernel(
    const float* __restrict__ em,          // [B,S,L]
    const int*   __restrict__ mask,        // [B,S]
    const int*   __restrict__ labels,      // [B,S] int32
    const float* __restrict__ start_t,     // [L]
    const float* __restrict__ end_t,       // [L]
    const float* __restrict__ trans)       // [L,L]
{
    const int b = blockIdx.x;
    const int j = threadIdx.x;

    __shared__ float4 qbuf4[2][L_ / 4];
    __shared__ float  red[L_];

    // ---- sequence length (mask is a prefix) ----
    {
        int cnt = 0;
        const int* mrow = mask + (size_t)b * S_;
        for (int t = j; t < S_; t += L_) cnt += mrow[t];
        red[j] = (float)cnt;
    }
    __syncthreads();
    #pragma unroll
    for (int s = 32; s > 0; s >>= 1) {
        if (j < s) red[j] += red[j + s];
        __syncthreads();
    }
    const int len = (int)red[0];
    __syncthreads();

    // ---- per-thread constants ----
    float E[L_];
    #pragma unroll
    for (int i = 0; i < L_; ++i)
        E[i] = __expf(trans[i * L_ + j]);
    const float eEnd = __expf(end_t[j]);

    const float* emb = em + (size_t)b * S_ * L_;

    // ---- init: alpha0 = start + em[0] ----
    const float alpha0 = start_t[j] + emb[j];
    ((float*)qbuf4[1])[j] = alpha0;
    __syncthreads();
    float m0v = -3.4e38f;
    #pragma unroll
    for (int i4 = 0; i4 < 16; ++i4) {
        const float4 v = qbuf4[1][i4];
        m0v = fmaxf(m0v, fmaxf(fmaxf(v.x, v.y), fmaxf(v.z, v.w)));
    }
    float c = m0v;
    ((float*)qbuf4[0])[j] = __expf(alpha0 - m0v);
    __syncthreads();

    // ---- main scan ----
    float pending = 1.0f;
    float em_cur = (len > 1) ? emb[(size_t)L_ + j] : 0.0f;
    int prev = 0;
    for (int t = 1; t < len; ++t) {
        const float em_next = (t + 1 < len) ? emb[(size_t)(t + 1) * L_ + j] : 0.0f;

        float v0 = 0.f, v1 = 0.f, v2 = 0.f, v3 = 0.f;
        const float4* qp = qbuf4[prev];
        #pragma unroll
        for (int i4 = 0; i4 < 16; ++i4) {
            const float4 q4 = qp[i4];
            v0 = fmaf(q4.x, E[i4 * 4 + 0], v0);
            v1 = fmaf(q4.y, E[i4 * 4 + 1], v1);
            v2 = fmaf(q4.z, E[i4 * 4 + 2], v2);
            v3 = fmaf(q4.w, E[i4 * 4 + 3], v3);
        }
        const float v = (v0 + v1) + (v2 + v3);
        const float q = v * __expf(em_cur) * pending;
        const int cur = prev ^ 1;
        ((float*)qbuf4[cur])[j] = q;
        __syncthreads();

        if ((t & 7) == 0) {
            float mx = 0.0f;
            #pragma unroll
            for (int i4 = 0; i4 < 16; ++i4) {
                const float4 u = qbuf4[cur][i4];
                mx = fmaxf(mx, fmaxf(fmaxf(u.x, u.y), fmaxf(u.z, u.w)));
            }
            pending = 1.0f / mx;
            c += __logf(mx);
        } else {
            pending = 1.0f;
        }
        em_cur = em_next;
        prev = cur;
    }

    // ---- log_z = c + log(pending) + log(sum_j q[j]*exp(end[j])) ----
    red[j] = ((float*)qbuf4[prev])[j] * eEnd;
    __syncthreads();
    #pragma unroll
    for (int s = 32; s > 0; s >>= 1) {
        if (j < s) red[j] += red[j + s];
        __syncthreads();
    }
    const float logz = c + __logf(pending) + __logf(red[0]);
    __syncthreads();

    // ---- numerator (parallel over t, strided); indices clamped to [0,63] ----
    const int* lab = labels + (size_t)b * S_;
    float part = 0.0f;
    for (int t = 1 + j; t < len; t += L_) {
        const int lp = lab[t - 1];
        const int lc = lab[t];
        const int tp = ((lp == -100) ? 0 : lp) & 63;
        const int tc = ((lc == -100) ? 0 : lc) & 63;
        part += trans[tp * L_ + tc] + emb[(size_t)t * L_ + tc];
    }
    if (j == 0) {
        const int l0 = lab[0];
        const int t0 = ((l0 == -100) ? 0 : l0) & 63;
        const int ll = lab[len - 1];
        const int tl = ((ll == -100) ? 0 : ll) & 63;
        part += start_t[t0] + emb[t0] + end_t[tl];
    }
    red[j] = part;
    __syncthreads();
    #pragma unroll
    for (int s = 32; s > 0; s >>= 1) {
        if (j < s) red[j] += red[j + s];
        __syncthreads();
    }
    if (j == 0) g_llh[b] = red[0] - logz;
}

// ================= loss reduce =================
__global__ void loss_kernel(float* __restrict__ out)
{
    __shared__ float r[B_];
    const int j = threadIdx.x;
    r[j] = g_llh[j];
    __syncthreads();
    #pragma unroll
    for (int s = 32; s > 0; s >>= 1) {
        if (j < s) r[j] += r[j + s];
        __syncthreads();
    }
    if (j == 0) out[0] = -r[0] / (float)B_;
}

// ================= launch =================
extern "C" void kernel_launch(void* const* d_in, const int* in_sizes, int n_in,
                              void* d_out, int out_size)
{
    const float* hs     = (const float*)d_in[0];
    const int*   mask   = (const int*)d_in[1];
    const int*   labels = (const int*)d_in[2];   // int64 in reference -> int32 on device
    const float* W      = (const float*)d_in[3];
    const float* bias   = (const float*)d_in[4];
    const float* st     = (const float*)d_in[5];
    const float* en     = (const float*)d_in[6];
    const float* tr     = (const float*)d_in[7];

    float* out = (float*)d_out;
    // Output layout: (loss, emissions) flattened -> loss at [0], emissions after
    const int off = (out_size > M_ * L_) ? (out_size - M_ * L_) : 0;
    float* emis = out + off;

    gemm_kernel<<<M_ / BM, 256>>>(hs, W, bias, emis);
    crf_kernel<<<B_, L_>>>(emis, mask, labels, st, en, tr);
    if (off > 0) loss_kernel<<<1, B_>>>(out);
}

// round 5
// speedup vs baseline: 1.0735x; 1.0735x over previous
#include <cuda_runtime.h>
#include <cstdint>

#define B_  64
#define S_  512
#define H_  1024
#define L_  64
#define M_  (B_ * S_)      // 32768 rows

typedef unsigned long long u64;

// ---------------- scratch (no allocations allowed) ----------------
__device__ float g_llh[B_];
__device__ int   g_done;     // zero-initialized; reset by last CTA each launch

// ---------------- f32x2 helpers (sm_100+, PTX ISA 8.6) ----------------
__device__ __forceinline__ u64 pack2(float lo, float hi) {
    u64 r;
    asm("mov.b64 %0, {%1, %2};" : "=l"(r) : "f"(lo), "f"(hi));
    return r;
}
__device__ __forceinline__ u64 dup2(float x) {
    u64 r;
    asm("mov.b64 %0, {%1, %1};" : "=l"(r) : "f"(x));
    return r;
}
__device__ __forceinline__ void fma2(u64 &d, u64 a, u64 b) {
    asm("fma.rn.f32x2 %0, %1, %2, %0;" : "+l"(d) : "l"(a), "l"(b));
}
__device__ __forceinline__ u64 add2(u64 a, u64 b) {
    u64 r;
    asm("add.rn.f32x2 %0, %1, %2;" : "=l"(r) : "l"(a), "l"(b));
    return r;
}
__device__ __forceinline__ float2 unpk2(u64 v) {
    float2 r;
    asm("mov.b64 {%0, %1}, %2;" : "=f"(r.x), "=f"(r.y) : "l"(v));
    return r;
}

// ================= Emissions GEMM (f32x2) =================
// emissions[m][l] = sum_k hs[m][k] * W[k][l] + bias[l]
// BM=128 x BN=64 (full L) x BK=16, 256 threads.
// Thread (tx=tid%16, ty=tid/16): rows ty*8..+7, cols tx*4..+3.
// Accumulators are col-pairs: acc[p][0] = cols (4tx,4tx+1), acc[p][1] = (4tx+2,4tx+3).
// B stored in smem as packed u64 col-pairs, interleaved: even pairs at [0..15], odd at [16..31]
// so each warp LDS.64 covers a contiguous 128B span (conflict-free).
#define BM 128
#define BN 64
#define BK 16
#define AS_ROW (BM / 4 + 1)   // float4 units per k-row (+1 pad)

__global__ __launch_bounds__(256) void gemm_kernel(
    const float* __restrict__ hs,
    const float* __restrict__ W,
    const float* __restrict__ bias,
    float* __restrict__ out)
{
    __shared__ float4 As4[BK][AS_ROW];   // transposed: As4[k][row/4]
    __shared__ u64    Bs2[BK][32];       // [k][interleaved col-pair]

    const int tid = threadIdx.x;
    const int m0  = blockIdx.x * BM;
    const int tx  = tid & 15;    // col group -> cols tx*4..+3
    const int ty  = tid >> 4;    // row group -> rows ty*8..+7

    // ---- global load mapping ----
    const int a_row = tid >> 2;          // 0..63
    const int a_k   = (tid & 3) * 4;     // 0,4,8,12
    const float* hsA0 = hs + (size_t)(m0 + a_row)      * H_ + a_k;
    const float* hsA1 = hs + (size_t)(m0 + a_row + 64) * H_ + a_k;
    const int b_k  = tid >> 4;           // 0..15
    const int b_c4 = tid & 15;           // 0..15
    const float* Wp = W + (size_t)b_k * L_ + b_c4 * 4;

    u64 acc[8][2];
    #pragma unroll
    for (int p = 0; p < 8; ++p) { acc[p][0] = 0ull; acc[p][1] = 0ull; }

    float4 a0 = *(const float4*)hsA0;
    float4 a1 = *(const float4*)hsA1;
    float4 bw = *(const float4*)Wp;

    float* As_f = (float*)As4;   // scalar alias for transposed staging

    const int NCH = H_ / BK;     // 64 chunks
    for (int kc = 0; kc < NCH; ++kc) {
        // stage A (transposed scalar stores)
        As_f[(a_k + 0) * (AS_ROW * 4) + a_row] = a0.x;
        As_f[(a_k + 1) * (AS_ROW * 4) + a_row] = a0.y;
        As_f[(a_k + 2) * (AS_ROW * 4) + a_row] = a0.z;
        As_f[(a_k + 3) * (AS_ROW * 4) + a_row] = a0.w;
        As_f[(a_k + 0) * (AS_ROW * 4) + a_row + 64] = a1.x;
        As_f[(a_k + 1) * (AS_ROW * 4) + a_row + 64] = a1.y;
        As_f[(a_k + 2) * (AS_ROW * 4) + a_row + 64] = a1.z;
        As_f[(a_k + 3) * (AS_ROW * 4) + a_row + 64] = a1.w;
        // stage B as packed pairs (even pair -> [b_c4], odd pair -> [16+b_c4])
        Bs2[b_k][b_c4]      = pack2(bw.x, bw.y);
        Bs2[b_k][16 + b_c4] = pack2(bw.z, bw.w);
        __syncthreads();

        if (kc + 1 < NCH) {
            a0 = *(const float4*)(hsA0 + (kc + 1) * BK);
            a1 = *(const float4*)(hsA1 + (kc + 1) * BK);
            bw = *(const float4*)(Wp + (size_t)(kc + 1) * BK * L_);
        }

        #pragma unroll
        for (int kk = 0; kk < BK; ++kk) {
            const float4 av0 = As4[kk][ty * 2];       // rows ty*8..+3 (broadcast)
            const float4 av1 = As4[kk][ty * 2 + 1];   // rows ty*8+4..+7
            const u64 b0 = Bs2[kk][tx];               // cols 4tx,4tx+1
            const u64 b1 = Bs2[kk][16 + tx];          // cols 4tx+2,4tx+3
            u64 ad[8];
            ad[0] = dup2(av0.x); ad[1] = dup2(av0.y);
            ad[2] = dup2(av0.z); ad[3] = dup2(av0.w);
            ad[4] = dup2(av1.x); ad[5] = dup2(av1.y);
            ad[6] = dup2(av1.z); ad[7] = dup2(av1.w);
            #pragma unroll
            for (int p = 0; p < 8; ++p) {
                fma2(acc[p][0], ad[p], b0);
                fma2(acc[p][1], ad[p], b1);
            }
        }
        __syncthreads();
    }

    // epilogue: add bias, scalar stores (emis base is only 4B-aligned: out+1)
    float bb[4];
    #pragma unroll
    for (int q = 0; q < 4; ++q) bb[q] = bias[tx * 4 + q];

    #pragma unroll
    for (int p = 0; p < 8; ++p) {
        const size_t r = (size_t)(m0 + ty * 8 + p) * L_ + tx * 4;
        const float2 c0 = unpk2(acc[p][0]);
        const float2 c1 = unpk2(acc[p][1]);
        out[r + 0] = c0.x + bb[0];
        out[r + 1] = c0.y + bb[1];
        out[r + 2] = c1.x + bb[2];
        out[r + 3] = c1.y + bb[3];
    }
}

// ================= CRF kernel (f32x2 scan, fused loss) =================
// One CTA per batch, 64 threads (thread j owns label j).
// Exp-domain scan: q_t[j] = (sum_i q_{t-1}[i] * E[i][j]) * exp(em[t][j]) * pending.
// E pairs held packed (32 x u64 per thread); q in shared as native ulonglong2[16]
// (scalar writes, LDS.128 reads). Renorm by block max every 8 steps.
__global__ __launch_bounds__(64) void crf_kernel(
    const float* __restrict__ em,          // [B,S,L]
    const int*   __restrict__ mask,        // [B,S]
    const int*   __restrict__ labels,      // [B,S] int32
    const float* __restrict__ start_t,     // [L]
    const float* __restrict__ end_t,       // [L]
    const float* __restrict__ trans,       // [L,L]
    float* __restrict__ loss_out)
{
    const int b = blockIdx.x;
    const int j = threadIdx.x;

    __shared__ ulonglong2 qb[2][L_ / 4];
    __shared__ float      red[L_];

    // ---- sequence length (mask is a prefix) ----
    {
        int cnt = 0;
        const int* mrow = mask + (size_t)b * S_;
        for (int t = j; t < S_; t += L_) cnt += mrow[t];
        red[j] = (float)cnt;
    }
    __syncthreads();
    #pragma unroll
    for (int s = 32; s > 0; s >>= 1) {
        if (j < s) red[j] += red[j + s];
        __syncthreads();
    }
    const int len = (int)red[0];
    __syncthreads();

    // ---- per-thread constants: packed E pairs ----
    u64 Ep[32];
    #pragma unroll
    for (int k = 0; k < 32; ++k)
        Ep[k] = pack2(__expf(trans[(2 * k) * L_ + j]),
                      __expf(trans[(2 * k + 1) * L_ + j]));
    const float eEnd = __expf(end_t[j]);

    const float* emb = em + (size_t)b * S_ * L_;

    // ---- init: alpha0 = start + em[0], renorm by block max ----
    const float alpha0 = start_t[j] + emb[j];
    red[j] = alpha0;
    __syncthreads();
    float m0v = -3.4e38f;
    #pragma unroll
    for (int i = 0; i < L_; ++i) m0v = fmaxf(m0v, red[i]);
    float c = m0v;
    ((float*)qb[0])[j] = __expf(alpha0 - m0v);
    __syncthreads();

    // ---- main scan (em prefetch depth 2) ----
    float pending = 1.0f;
    float emA = (len > 1) ? emb[(size_t)1 * L_ + j] : 0.0f;
    float emB = (len > 2) ? emb[(size_t)2 * L_ + j] : 0.0f;
    int prev = 0;
    for (int t = 1; t < len; ++t) {
        const float em_cur = emA;
        emA = emB;
        emB = (t + 2 < len) ? emb[(size_t)(t + 2) * L_ + j] : 0.0f;

        u64 a8[8];
        #pragma unroll
        for (int k = 0; k < 8; ++k) a8[k] = 0ull;
        const ulonglong2* qp = qb[prev];
        #pragma unroll
        for (int i = 0; i < 16; ++i) {
            const ulonglong2 u = qp[i];
            fma2(a8[(2 * i) & 7],     u.x, Ep[2 * i]);
            fma2(a8[(2 * i + 1) & 7], u.y, Ep[2 * i + 1]);
        }
        const u64 s0 = add2(add2(a8[0], a8[4]), add2(a8[2], a8[6]));
        const u64 s1 = add2(add2(a8[1], a8[5]), add2(a8[3], a8[7]));
        const float2 vv = unpk2(add2(s0, s1));
        const float v = vv.x + vv.y;

        const float q = v * __expf(em_cur) * pending;
        const int cur = prev ^ 1;
        ((float*)qb[cur])[j] = q;
        __syncthreads();

        if ((t & 7) == 0) {
            float mx = 0.0f;
            #pragma unroll
            for (int i = 0; i < 16; ++i) {
                const ulonglong2 u = qb[cur][i];
                const float2 f0 = unpk2(u.x);
                const float2 f1 = unpk2(u.y);
                mx = fmaxf(mx, fmaxf(fmaxf(f0.x, f0.y), fmaxf(f1.x, f1.y)));
            }
            pending = 1.0f / mx;
            c += __logf(mx);
        } else {
            pending = 1.0f;
        }
        prev = cur;
    }

    // ---- log_z = c + log(pending) + log(sum_j q[j]*exp(end[j])) ----
    red[j] = ((float*)qb[prev])[j] * eEnd;
    __syncthreads();
    #pragma unroll
    for (int s = 32; s > 0; s >>= 1) {
        if (j < s) red[j] += red[j + s];
        __syncthreads();
    }
    const float logz = c + __logf(pending) + __logf(red[0]);
    __syncthreads();

    // ---- numerator (parallel over t, strided); indices clamped ----
    const int* lab = labels + (size_t)b * S_;
    float part = 0.0f;
    for (int t = 1 + j; t < len; t += L_) {
        const int lp = lab[t - 1];
        const int lc = lab[t];
        const int tp = ((lp == -100) ? 0 : lp) & 63;
        const int tc = ((lc == -100) ? 0 : lc) & 63;
        part += trans[tp * L_ + tc] + emb[(size_t)t * L_ + tc];
    }
    if (j == 0) {
        const int l0 = lab[0];
        const int t0 = ((l0 == -100) ? 0 : l0) & 63;
        const int ll = lab[len - 1];
        const int tl = ((ll == -100) ? 0 : ll) & 63;
        part += start_t[t0] + emb[t0] + end_t[tl];
    }
    red[j] = part;
    __syncthreads();
    #pragma unroll
    for (int s = 32; s > 0; s >>= 1) {
        if (j < s) red[j] += red[j + s];
        __syncthreads();
    }

    // ---- fused loss: last CTA to finish reduces all llh ----
    if (j == 0) {
        g_llh[b] = red[0] - logz;
        __threadfence();
        const int old = atomicAdd(&g_done, 1);
        if (old == B_ - 1) {
            float sum = 0.0f;
            #pragma unroll 8
            for (int i = 0; i < B_; ++i) sum += __ldcg(&g_llh[i]);
            loss_out[0] = -sum / (float)B_;
            g_done = 0;   // reset for next graph replay
        }
    }
}

// ================= launch =================
extern "C" void kernel_launch(void* const* d_in, const int* in_sizes, int n_in,
                              void* d_out, int out_size)
{
    const float* hs     = (const float*)d_in[0];
    const int*   mask   = (const int*)d_in[1];
    const int*   labels = (const int*)d_in[2];   // int64 in reference -> int32 on device
    const float* W      = (const float*)d_in[3];
    const float* bias   = (const float*)d_in[4];
    const float* st     = (const float*)d_in[5];
    const float* en     = (const float*)d_in[6];
    const float* tr     = (const float*)d_in[7];

    float* out = (float*)d_out;
    // Output layout: (loss, emissions) flattened -> loss at [0], emissions after
    const int off = (out_size > M_ * L_) ? (out_size - M_ * L_) : 0;
    float* emis = out + off;

    gemm_kernel<<<M_ / BM, 256>>>(hs, W, bias, emis);
    crf_kernel<<<B_, L_>>>(emis, mask, labels, st, en, tr, out);
}